// round 14
// baseline (speedup 1.0000x reference)
#include <cuda_runtime.h>

// LatticeQuantizer: hierarchical nested E8 lattice quantize (M=3, Q=4).
// R14 = R13 decision logic (proven) + R11 packed f32x2 arithmetic (proven
// bit-exact; R11 passed rel_err 0.0) with the R11 perf bug removed: no
// struct/aggregate-by-reference (that forced local-memory spills, L1 36%).
// Plain local arrays + forceinline array params only (R10/R13-proven safe).

typedef unsigned long long u64;

#define H2C   0x3F0000003F000000ULL   // (0.5f, 0.5f)
#define MH2C  0xBF000000BF000000ULL   // (-0.5f, -0.5f)
#define M1C   0xBF800000BF800000ULL   // (-1.0f, -1.0f)
#define Q2C   0x3E8000003E800000ULL   // (0.25f, 0.25f)
#define TINY_F 1.1920928955078125e-07f

static __device__ __forceinline__ u64 PK(float lo, float hi) {
    u64 r; asm("mov.b64 %0, {%1, %2};" : "=l"(r) : "f"(lo), "f"(hi)); return r;
}
static __device__ __forceinline__ void UPK(u64 v, float& lo, float& hi) {
    asm("mov.b64 {%0, %1}, %2;" : "=f"(lo), "=f"(hi) : "l"(v));
}
static __device__ __forceinline__ u64 ADD2(u64 a, u64 b) {
    u64 r; asm("add.rn.f32x2 %0, %1, %2;" : "=l"(r) : "l"(a), "l"(b)); return r;
}
static __device__ __forceinline__ u64 FMA2(u64 a, u64 b, u64 c) {
    u64 r; asm("fma.rn.f32x2 %0, %1, %2, %3;" : "=l"(r) : "l"(a), "l"(b), "l"(c)); return r;
}
static __device__ __forceinline__ u64 MUL2(u64 a, u64 b) {
    u64 r; asm("mul.rn.f32x2 %0, %1, %2;" : "=l"(r) : "l"(a), "l"(b)); return r;
}

// scalar faithful round (b block)
static __device__ __forceinline__ float cround(float x) {
    float s = copysignf(TINY_F, x);
    return floorf((x - s) + 0.5f);
}

// packed custom_round: per lane floor(fl(fl(x - copysign(tiny,x)) + 0.5))
// (numerics proven in R11 pass)
static __device__ __forceinline__ u64 cround2(u64 x2) {
    u64 ns2 = ((~x2) & 0x8000000080000000ULL) | 0x3400000034000000ULL;
    u64 v2  = ADD2(ADD2(x2, ns2), H2C);
    float vl, vh; UPK(v2, vl, vh);
    return PK(floorf(vl), floorf(vh));
}

// left-priority (FIRST max) tree argmax over 8 lanes (R13-proven)
static __device__ __forceinline__ void argmax8(const float r[8], float& rk, int& k)
{
    bool p01 = fabsf(r[1]) > fabsf(r[0]);
    float v01 = p01 ? r[1] : r[0];  int k01 = p01 ? 1 : 0;
    bool p23 = fabsf(r[3]) > fabsf(r[2]);
    float v23 = p23 ? r[3] : r[2];  int k23 = p23 ? 3 : 2;
    bool p45 = fabsf(r[5]) > fabsf(r[4]);
    float v45 = p45 ? r[5] : r[4];  int k45 = p45 ? 5 : 4;
    bool p67 = fabsf(r[7]) > fabsf(r[6]);
    float v67 = p67 ? r[7] : r[6];  int k67 = p67 ? 7 : 6;

    bool g0 = fabsf(v23) > fabsf(v01);
    float va = g0 ? v23 : v01;  int ka = g0 ? k23 : k01;
    bool g1 = fabsf(v67) > fabsf(v45);
    float vb = g1 ? v67 : v45;  int kb = g1 ? k67 : k45;

    bool gf = fabsf(vb) > fabsf(va);
    rk = gf ? vb : va;
    k  = gf ? kb : ka;
}

// ---- encode-path closest point ----
static __device__ __forceinline__ void cp_e8_enc(const u64 t2[4], float out[8])
{
    float x[8];
#pragma unroll
    for (int p = 0; p < 4; p++) UPK(t2[p], x[2*p], x[2*p+1]);

    // candidate A (packed round + residual; per-lane bit-identical)
    u64 fA2[4], rA2[4];
    float fA[8], rA[8];
#pragma unroll
    for (int p = 0; p < 4; p++) {
        fA2[p] = cround2(t2[p]);
        rA2[p] = FMA2(fA2[p], M1C, t2[p]);   // fl(x - f), exact
        UPK(fA2[p], fA[2*p], fA[2*p+1]);
        UPK(rA2[p], rA[2*p], rA[2*p+1]);
    }
    u64 sA2 = ADD2(ADD2(fA2[0], fA2[1]), ADD2(fA2[2], fA2[3]));
    float sAl, sAh; UPK(sA2, sAl, sAh);
    float sA = sAl + sAh;                    // exact ints: tree-safe (R11)

    float rkA; int kA;
    argmax8(rA, rkA, kA);
    float tieA  = (x[0] >= 0.f) ? -1.f : 1.f;   // rk==0 => all r==0 => k==0
    float stepA = (rkA > 0.f) ? 1.f : ((rkA < 0.f) ? -1.f : tieA);
    bool oddA = (((int)sA) & 1) != 0;
    int  kAe  = oddA ? kA : 8;
    float rcA = rkA - stepA;

    // candidate B (packed xs/round; decisions scalar)
    u64 fB2[4];
    float fB[8], rB[8];
#pragma unroll
    for (int p = 0; p < 4; p++) {
        u64 xs2 = ADD2(t2[p], MH2C);         // fl(x - 0.5) per lane
        fB2[p]  = cround2(xs2);
        u64 rB2 = FMA2(fB2[p], M1C, xs2);    // xs - fB, exact
        UPK(fB2[p], fB[2*p], fB[2*p+1]);
        UPK(rB2,    rB[2*p], rB[2*p+1]);
    }
    u64 sB2 = ADD2(ADD2(fB2[0], fB2[1]), ADD2(fB2[2], fB2[3]));
    float sBl, sBh; UPK(sB2, sBl, sBh);
    float sB = sBl + sBh;

    float rkB; int kB;
    argmax8(rB, rkB, kB);
    float tieB  = ((x[0] - 0.5f) >= 0.f) ? -1.f : 1.f;
    float stepB = (rkB > 0.f) ? 1.f : ((rkB < 0.f) ? -1.f : tieB);
    bool oddB = (((int)sB) & 1) != 0;
    int  kBe  = oddB ? kB : 8;

    // yB = fB + (addB + 0.5): exact half-int adds (R12/R13-proven)
    float stepB_h = stepB + 0.5f;
    float d0 = 0.f, d1 = 0.f;
    float yB[8];
#pragma unroll
    for (int i = 0; i < 8; i++) {
        float addBh = (i == kBe) ? stepB_h : 0.5f;
        yB[i] = fB[i] + addBh;
        float a  = (i == kAe) ? rcA : rA[i];
        float rb = x[i] - yB[i];
        d0 = __fadd_rn(d0, __fmul_rn(a, a));   // reference sequential order
        d1 = __fadd_rn(d1, __fmul_rn(rb, rb));
    }
    bool p0 = d0 < d1;
#pragma unroll
    for (int i = 0; i < 8; i++) {
        float oA = fA[i];                      // reference: f + 0*step == f
        if (i == kAe) oA += stepA;
        out[i] = p0 ? oA : yB[i];
    }
}

// ---- decode-path residuals: v = gq - cp_e8(gq), exact eighths domain ----
static __device__ __forceinline__ void cp_e8_dec_res(const u64 x2[4], float v[8])
{
    float x0lo, x0hi; UPK(x2[0], x0lo, x0hi);

    u64 rA2[4]; float rA[8];
#pragma unroll
    for (int p = 0; p < 4; p++) {
        u64 f2 = cround2(x2[p]);
        rA2[p] = FMA2(f2, M1C, x2[p]);
        UPK(rA2[p], rA[2*p], rA[2*p+1]);
        if (p == 0) { /* sums accumulated below */ }
    }
    // sums (exact small ints, tree-safe)
    u64 sA2 = 0ull, sB2 = 0ull;
    u64 rB2[4]; float rB[8];
#pragma unroll
    for (int p = 0; p < 4; p++) {
        u64 f2 = cround2(x2[p]);             // CSE'd with above by compiler
        sA2 = ADD2(sA2, f2);
        u64 xs2 = ADD2(x2[p], MH2C);         // exact here (x on 1/8 grid)
        u64 g2  = cround2(xs2);
        sB2 = ADD2(sB2, g2);
        rB2[p] = FMA2(g2, M1C, xs2);
        UPK(rB2[p], rB[2*p], rB[2*p+1]);
    }
    float sl, sh;
    UPK(sA2, sl, sh); float sA = sl + sh;
    UPK(sB2, sl, sh); float sB = sl + sh;

    float rkA; int kA;
    argmax8(rA, rkA, kA);
    float tieA  = (x0lo >= 0.f) ? -1.f : 1.f;
    float stepA = (rkA > 0.f) ? 1.f : ((rkA < 0.f) ? -1.f : tieA);
    bool oddA = (((int)sA) & 1) != 0;
    int  kAe  = oddA ? kA : 8;
    float rcA = rkA - stepA;

    float rkB; int kB;
    argmax8(rB, rkB, kB);
    float tieB  = ((x0lo - 0.5f) >= 0.f) ? -1.f : 1.f;
    float stepB = (rkB > 0.f) ? 1.f : ((rkB < 0.f) ? -1.f : tieB);
    bool oddB = (((int)sB) & 1) != 0;
    int  kBe  = oddB ? kB : 8;
    float rcB = rkB - stepB;

    // exact-domain distances: packed FMA + tie adjustment (R11-proven)
    u64 dA2 = 0ull, dB2 = 0ull;
#pragma unroll
    for (int p = 0; p < 4; p++) {
        dA2 = FMA2(rA2[p], rA2[p], dA2);
        dB2 = FMA2(rB2[p], rB2[p], dB2);
    }
    float al, ah, bl, bh;
    UPK(dA2, al, ah); UPK(dB2, bl, bh);
    float d0 = al + ah;
    float d1 = bl + bh;
    float adjA = __fmul_rn(rcA, rcA) - __fmul_rn(rkA, rkA);  // exact
    float adjB = __fmul_rn(rcB, rcB) - __fmul_rn(rkB, rkB);
    d0 += oddA ? adjA : 0.f;
    d1 += oddB ? adjB : 0.f;
    bool p0 = d0 < d1;

    int   ksel = p0 ? kAe : kBe;
    float rcs  = p0 ? rcA : rcB;
#pragma unroll
    for (int i = 0; i < 8; i++) {
        float rs = p0 ? rA[i] : rB[i];
        v[i] = (i == ksel) ? rcs : rs;
    }
}

__global__ void __launch_bounds__(256)
lq_kernel(const float4* __restrict__ xin,
          const float* __restrict__ betap,
          const float* __restrict__ epsp,
          float4* __restrict__ outp,
          int nrows)
{
    int row = blockIdx.x * blockDim.x + threadIdx.x;
    if (row >= nrows) return;

    float beta = __ldg(betap);
    bool beta1 = (beta == 1.0f);
    u64 eps2[4];
#pragma unroll
    for (int p = 0; p < 4; p++)
        eps2[p] = PK(__ldg(epsp + 2*p), __ldg(epsp + 2*p + 1));

    float4 a0 = __ldg(xin + 2 * row);
    float4 a1 = __ldg(xin + 2 * row + 1);
    float x[8] = {a0.x, a0.y, a0.z, a0.w, a1.x, a1.y, a1.z, a1.w};

    // layer-0 encode input: t = x/beta + eps (x/1.0 == x bitwise)
    u64 t2[4];
#pragma unroll
    for (int p = 0; p < 4; p++) {
        float l0 = beta1 ? x[2*p]   : __fdiv_rn(x[2*p],   beta);
        float l1 = beta1 ? x[2*p+1] : __fdiv_rn(x[2*p+1], beta);
        t2[p] = ADD2(PK(l0, l1), eps2[p]);
    }

    float xh[8] = {0.f, 0.f, 0.f, 0.f, 0.f, 0.f, 0.f, 0.f};

#pragma unroll
    for (int m = 0; m < 3; m++) {
        // ---- encode layer m ----
        float cp[8];
        cp_e8_enc(t2, cp);

        // z = cp @ G_inv (analytic forward solve; exact quarter-integers)
        float z[8];
        z[0] = 0.5f * cp[0];
        float sum06 = z[0];
#pragma unroll
        for (int i = 1; i < 7; i++) { z[i] = cp[i] + z[i - 1]; sum06 += z[i]; }
        z[7] = 2.f * cp[7] - sum06;

        // b = custom_round(fmod(z,4)); fmod exact; cround REQUIRED
        float b[8];
#pragma unroll
        for (int i = 0; i < 8; i++) {
            float q = truncf(z[i] * 0.25f);
            float r = __fmaf_rn(-4.f, q, z[i]);   // exact (dyadic)
            b[i] = cround(r);
        }

        // next layer: t = fma(cp, 1/Q, eps) == fl(fl(cp*0.25)+eps) (R11-proven)
        if (m < 2) {
#pragma unroll
            for (int p = 0; p < 4; p++)
                t2[p] = FMA2(PK(cp[2*p], cp[2*p+1]), Q2C, eps2[p]);
        }

        // ---- decode layer m: xi = g - 4*cp_e8(g/4) == 4*v ----
        float h = 0.5f * b[7];
        float g[8];
        g[0] = 2.f * b[0] - b[1] + h;
#pragma unroll
        for (int j = 1; j < 6; j++) g[j] = b[j] - b[j + 1] + h;
        g[6] = b[6] + h;
        g[7] = h;

        u64 gq2[4];
#pragma unroll
        for (int p = 0; p < 4; p++)
            gq2[p] = MUL2(PK(g[2*p], g[2*p+1]), Q2C);   // exact eighths

        float v[8];
        cp_e8_dec_res(gq2, v);

        float c4 = (m == 0) ? 4.f : ((m == 1) ? 16.f : 64.f);
#pragma unroll
        for (int i = 0; i < 8; i++)
            xh[i] = __fmaf_rn(c4, v[i], xh[i]);         // exact dyadic
    }

    float4 o0, o1;
    if (beta1) {
        o0 = make_float4(xh[0], xh[1], xh[2], xh[3]);
        o1 = make_float4(xh[4], xh[5], xh[6], xh[7]);
    } else {
        o0 = make_float4(beta*xh[0], beta*xh[1], beta*xh[2], beta*xh[3]);
        o1 = make_float4(beta*xh[4], beta*xh[5], beta*xh[6], beta*xh[7]);
    }
    outp[2 * row]     = o0;
    outp[2 * row + 1] = o1;
}

extern "C" void kernel_launch(void* const* d_in, const int* in_sizes, int n_in,
                              void* d_out, int out_size)
{
    const float* x = (const float*)d_in[0];
    const float* beta = nullptr;
    const float* eps  = nullptr;
    for (int i = 1; i < n_in; i++) {
        if (in_sizes[i] == 1) beta = (const float*)d_in[i];
        else if (in_sizes[i] == 8) eps = (const float*)d_in[i];
    }
    int nrows = in_sizes[0] / 8;
    int threads = 256;
    int blocks = (nrows + threads - 1) / threads;
    lq_kernel<<<blocks, threads>>>((const float4*)x, beta, eps, (float4*)d_out, nrows);
}

// round 15
// speedup vs baseline: 1.0111x; 1.0111x over previous
#include <cuda_runtime.h>

// LatticeQuantizer: hierarchical nested E8 lattice quantize (M=3, Q=4).
// R15 = R13 (best scalar baseline) + three exact micro-cuts:
//  - bit-trick step sign (tie -0.0 case proven impossible at all sites)
//  - decode tie adjustment via exact difference-of-squares
//  - layer-0 xh direct product
// f32x2 retired (R11 spilled, R14 neutral); >1 row/thread retired (R12).

#define TINY_F 1.1920928955078125e-07f  // np.finfo(float32).eps

static __device__ __forceinline__ float cround(float x) {
    float s = copysignf(TINY_F, x);
    return floorf((x - s) + 0.5f);
}

// left-priority (FIRST max) tree argmax over 8 lanes (R13-proven)
static __device__ __forceinline__ void argmax8(const float r[8], float& rk, int& k)
{
    bool p01 = fabsf(r[1]) > fabsf(r[0]);
    float v01 = p01 ? r[1] : r[0];  int k01 = p01 ? 1 : 0;
    bool p23 = fabsf(r[3]) > fabsf(r[2]);
    float v23 = p23 ? r[3] : r[2];  int k23 = p23 ? 3 : 2;
    bool p45 = fabsf(r[5]) > fabsf(r[4]);
    float v45 = p45 ? r[5] : r[4];  int k45 = p45 ? 5 : 4;
    bool p67 = fabsf(r[7]) > fabsf(r[6]);
    float v67 = p67 ? r[7] : r[6];  int k67 = p67 ? 7 : 6;

    bool g0 = fabsf(v23) > fabsf(v01);
    float va = g0 ? v23 : v01;  int ka = g0 ? k23 : k01;
    bool g1 = fabsf(v67) > fabsf(v45);
    float vb = g1 ? v67 : v45;  int kb = g1 ? k67 : k45;

    bool gf = fabsf(vb) > fabsf(va);
    rk = gf ? vb : va;
    k  = gf ? kb : ka;
}

// step: rk>0 -> +1 ; rk<0 -> -1 ; rk==0 -> (x0>=0 ? -1 : +1)
// (rk==0 implies all residuals 0 and k==0, so the tie coord is lane 0;
//  x0 == -0.0 proven impossible at every call site.)
static __device__ __forceinline__ float stepsign(float rk, float x0) {
    int sel = (rk == 0.f) ? (__float_as_int(x0) ^ 0x80000000)
                          : __float_as_int(rk);
    return __int_as_float((sel & 0x80000000) | 0x3f800000);
}

// ---- encode-path closest point (decision numerics R13-verbatim) ----
static __device__ __forceinline__ void cp_e8_enc(const float x[8], float out[8]) {
    float fA[8], rA[8]; float sA = 0.f;
#pragma unroll
    for (int i = 0; i < 8; i++) {
        fA[i] = cround(x[i]);
        rA[i] = x[i] - fA[i];      // exact
        sA += fA[i];               // exact (small ints)
    }
    float rkA; int kA;
    argmax8(rA, rkA, kA);
    float stepA = stepsign(rkA, x[0]);
    bool oddA = (((int)sA) & 1) != 0;
    int  kAe  = oddA ? kA : 8;
    float rcA = rkA - stepA;       // fl == fl(x_k - (fA_k + step))

    float fB[8], rB[8]; float sB = 0.f;
#pragma unroll
    for (int i = 0; i < 8; i++) {
        float xs = x[i] - 0.5f;    // reference computes the same fl
        fB[i] = cround(xs);
        rB[i] = xs - fB[i];        // exact relative to xs
        sB += fB[i];
    }
    float rkB; int kB;
    argmax8(rB, rkB, kB);
    float stepB = stepsign(rkB, x[0] - 0.5f);
    bool oddB = (((int)sB) & 1) != 0;
    int  kBe  = oddB ? kB : 8;

    // yB = (fB + addB) + 0.5 == fB + (addB + 0.5): exact half-int adds
    float stepB_h = stepB + 0.5f;  // exact
    float d0 = 0.f, d1 = 0.f;
    float yB[8];
#pragma unroll
    for (int i = 0; i < 8; i++) {
        float addBh = (i == kBe) ? stepB_h : 0.5f;
        yB[i] = fB[i] + addBh;                 // exact, == reference value
        float a  = (i == kAe) ? rcA : rA[i];
        float rb = x[i] - yB[i];
        d0 = __fadd_rn(d0, __fmul_rn(a, a));   // reference sequential order
        d1 = __fadd_rn(d1, __fmul_rn(rb, rb));
    }
    bool p0 = d0 < d1;
#pragma unroll
    for (int i = 0; i < 8; i++) {
        float oA = fA[i];                      // reference: f + 0*step == f
        if (i == kAe) oA += stepA;             // exact +-1 at flip lane
        out[i] = p0 ? oA : yB[i];
    }
}

// ---- decode-path residuals: v = gq - cp_e8(gq) (exact eighths domain) ----
static __device__ __forceinline__ void cp_e8_dec_res(const float x[8], float v[8]) {
    float rA[8]; float sA = 0.f;
#pragma unroll
    for (int i = 0; i < 8; i++) {
        float f = cround(x[i]);
        rA[i] = x[i] - f;
        sA += f;
    }
    float rkA; int kA;
    argmax8(rA, rkA, kA);
    float stepA = stepsign(rkA, x[0]);
    bool oddA = (((int)sA) & 1) != 0;
    int  kAe  = oddA ? kA : 8;
    float rcA = rkA - stepA;

    float rB[8]; float sB = 0.f;
#pragma unroll
    for (int i = 0; i < 8; i++) {
        float xs = x[i] - 0.5f;    // exact here (x on 1/8 grid)
        float f  = cround(xs);
        rB[i] = xs - f;
        sB += f;
    }
    float rkB; int kB;
    argmax8(rB, rkB, kB);
    float stepB = stepsign(rkB, x[0] - 0.5f);
    bool oddB = (((int)sB) & 1) != 0;
    int  kBe  = oddB ? kB : 8;
    float rcB = rkB - stepB;

    // exact-domain distances (bisect-proven order-free):
    // adj = rc^2 - rk^2 == -(step*(rc+rk)); all values exact dyadic.
    float d0 = 0.f, d1 = 0.f;
#pragma unroll
    for (int i = 0; i < 8; i++) {
        d0 = __fmaf_rn(rA[i], rA[i], d0);
        d1 = __fmaf_rn(rB[i], rB[i], d1);
    }
    float adjA = __fmul_rn(stepA, rcA + rkA);   // exact; == rk^2 - rc^2
    float adjB = __fmul_rn(stepB, rcB + rkB);
    d0 = oddA ? (d0 - adjA) : d0;               // exact subtraction
    d1 = oddB ? (d1 - adjB) : d1;
    bool p0 = d0 < d1;

    int   ksel = p0 ? kAe : kBe;
    float rcs  = p0 ? rcA : rcB;
#pragma unroll
    for (int i = 0; i < 8; i++) {
        float rs = p0 ? rA[i] : rB[i];
        v[i] = (i == ksel) ? rcs : rs;
    }
}

__global__ void __launch_bounds__(256)
lq_kernel(const float4* __restrict__ xin,
          const float* __restrict__ betap,
          const float* __restrict__ epsp,
          float4* __restrict__ outp,
          int nrows)
{
    int row = blockIdx.x * blockDim.x + threadIdx.x;
    if (row >= nrows) return;

    float beta = __ldg(betap);
    float eps[8];
#pragma unroll
    for (int i = 0; i < 8; i++) eps[i] = __ldg(epsp + i);

    float4 a0 = __ldg(xin + 2 * row);
    float4 a1 = __ldg(xin + 2 * row + 1);
    float x[8] = {a0.x, a0.y, a0.z, a0.w, a1.x, a1.y, a1.z, a1.w};

    bool beta1 = (beta == 1.0f);

    // layer-0 encode input: t = x/beta + eps (x/1.0 == x bitwise)
    float t[8];
#pragma unroll
    for (int i = 0; i < 8; i++) {
        float xl = beta1 ? x[i] : __fdiv_rn(x[i], beta);
        t[i] = xl + eps[i];
    }

    float xh[8];

#pragma unroll
    for (int m = 0; m < 3; m++) {
        // ---- encode layer m ----
        float cp[8];
        cp_e8_enc(t, cp);

        // z = cp @ G_inv (analytic forward solve; exact quarter-integers)
        float z[8];
        z[0] = 0.5f * cp[0];
        float sum06 = z[0];
#pragma unroll
        for (int i = 1; i < 7; i++) { z[i] = cp[i] + z[i - 1]; sum06 += z[i]; }
        z[7] = 2.f * cp[7] - sum06;

        // b = custom_round(fmod(z,4)); fmod exact; cround REQUIRED
        float b[8];
#pragma unroll
        for (int i = 0; i < 8; i++) {
            float q = truncf(z[i] * 0.25f);
            float r = __fmaf_rn(-4.f, q, z[i]);   // exact (dyadic)
            b[i] = cround(r);
        }

        // next layer input: t = fma(cp, 1/Q, eps) == fl(fl(cp*0.25)+eps)
        if (m < 2) {
#pragma unroll
            for (int i = 0; i < 8; i++)
                t[i] = __fmaf_rn(cp[i], 0.25f, eps[i]);
        }

        // ---- decode layer m: xi = g - 4*cp_e8(g/4) == 4*v ----
        float h = 0.5f * b[7];
        float g[8];
        g[0] = 2.f * b[0] - b[1] + h;
#pragma unroll
        for (int j = 1; j < 6; j++) g[j] = b[j] - b[j + 1] + h;
        g[6] = b[6] + h;
        g[7] = h;

        float gq[8];
#pragma unroll
        for (int i = 0; i < 8; i++) gq[i] = g[i] * 0.25f;   // exact eighths
        float v[8];
        cp_e8_dec_res(gq, v);

        // xh += 4^(m+1) * v — all exact dyadic
        if (m == 0) {
#pragma unroll
            for (int i = 0; i < 8; i++) xh[i] = __fmul_rn(4.f, v[i]);
        } else {
            float c4 = (m == 1) ? 16.f : 64.f;
#pragma unroll
            for (int i = 0; i < 8; i++)
                xh[i] = __fmaf_rn(c4, v[i], xh[i]);
        }
    }

    float4 o0, o1;
    if (beta1) {
        o0 = make_float4(xh[0], xh[1], xh[2], xh[3]);
        o1 = make_float4(xh[4], xh[5], xh[6], xh[7]);
    } else {
        o0 = make_float4(beta*xh[0], beta*xh[1], beta*xh[2], beta*xh[3]);
        o1 = make_float4(beta*xh[4], beta*xh[5], beta*xh[6], beta*xh[7]);
    }
    outp[2 * row]     = o0;
    outp[2 * row + 1] = o1;
}

extern "C" void kernel_launch(void* const* d_in, const int* in_sizes, int n_in,
                              void* d_out, int out_size)
{
    const float* x = (const float*)d_in[0];
    const float* beta = nullptr;
    const float* eps  = nullptr;
    for (int i = 1; i < n_in; i++) {
        if (in_sizes[i] == 1) beta = (const float*)d_in[i];
        else if (in_sizes[i] == 8) eps = (const float*)d_in[i];
    }
    int nrows = in_sizes[0] / 8;
    int threads = 256;
    int blocks = (nrows + threads - 1) / threads;
    lq_kernel<<<blocks, threads>>>((const float4*)x, beta, eps, (float4*)d_out, nrows);
}

// round 16
// speedup vs baseline: 1.0500x; 1.0384x over previous
#include <cuda_runtime.h>

// LatticeQuantizer: hierarchical nested E8 lattice quantize (M=3, Q=4).
// R16 = R15 + new proven exactness: for layers m>=1, t = fl(cp/4 + eps) is
// EXACTLY on the 1/8 grid (eps ~2^-41 absorbed; cp==0 lanes carry t=eps_i,
// audited harmless: absorbed in all downstream fl's, and it reproduces the
// reference's tie-dither argmax in all-zero rows). So encode layers 1-2 use
// the exact-domain cp_e8 (FMA distances, residual outputs) — only layer 0
// needs the reference-order encode path. Parity sums tree-ified (exact ints).

#define TINY_F 1.1920928955078125e-07f  // np.finfo(float32).eps

static __device__ __forceinline__ float cround(float x) {
    float s = copysignf(TINY_F, x);
    return floorf((x - s) + 0.5f);
}

// left-priority (FIRST max) tree argmax over 8 lanes (R13-proven)
static __device__ __forceinline__ void argmax8(const float r[8], float& rk, int& k)
{
    bool p01 = fabsf(r[1]) > fabsf(r[0]);
    float v01 = p01 ? r[1] : r[0];  int k01 = p01 ? 1 : 0;
    bool p23 = fabsf(r[3]) > fabsf(r[2]);
    float v23 = p23 ? r[3] : r[2];  int k23 = p23 ? 3 : 2;
    bool p45 = fabsf(r[5]) > fabsf(r[4]);
    float v45 = p45 ? r[5] : r[4];  int k45 = p45 ? 5 : 4;
    bool p67 = fabsf(r[7]) > fabsf(r[6]);
    float v67 = p67 ? r[7] : r[6];  int k67 = p67 ? 7 : 6;

    bool g0 = fabsf(v23) > fabsf(v01);
    float va = g0 ? v23 : v01;  int ka = g0 ? k23 : k01;
    bool g1 = fabsf(v67) > fabsf(v45);
    float vb = g1 ? v67 : v45;  int kb = g1 ? k67 : k45;

    bool gf = fabsf(vb) > fabsf(va);
    rk = gf ? vb : va;
    k  = gf ? kb : ka;
}

// step: rk>0 -> +1 ; rk<0 -> -1 ; rk==0 -> (x0>=0 ? -1 : +1)
// (rk==0 implies all residuals 0 and k==0; x0==-0.0 impossible at all sites)
static __device__ __forceinline__ float stepsign(float rk, float x0) {
    int sel = (rk == 0.f) ? (__float_as_int(x0) ^ 0x80000000)
                          : __float_as_int(rk);
    return __int_as_float((sel & 0x80000000) | 0x3f800000);
}

// exact 8-way tree sum (integers: any association bit-identical)
static __device__ __forceinline__ float tsum8(const float f[8]) {
    float s01 = f[0] + f[1], s23 = f[2] + f[3];
    float s45 = f[4] + f[5], s67 = f[6] + f[7];
    return (s01 + s23) + (s45 + s67);
}

// ---- layer-0 encode closest point (reference-order; R15-verbatim) ----
static __device__ __forceinline__ void cp_e8_enc(const float x[8], float out[8]) {
    float fA[8], rA[8];
#pragma unroll
    for (int i = 0; i < 8; i++) {
        fA[i] = cround(x[i]);
        rA[i] = x[i] - fA[i];      // exact
    }
    float sA = tsum8(fA);          // exact ints, tree-safe
    float rkA; int kA;
    argmax8(rA, rkA, kA);
    float stepA = stepsign(rkA, x[0]);
    bool oddA = (((int)sA) & 1) != 0;
    int  kAe  = oddA ? kA : 8;
    float rcA = rkA - stepA;       // fl == fl(x_k - (fA_k + step))

    float fB[8], rB[8];
#pragma unroll
    for (int i = 0; i < 8; i++) {
        float xs = x[i] - 0.5f;    // reference computes the same fl
        fB[i] = cround(xs);
        rB[i] = xs - fB[i];
    }
    float sB = tsum8(fB);
    float rkB; int kB;
    argmax8(rB, rkB, kB);
    float stepB = stepsign(rkB, x[0] - 0.5f);
    bool oddB = (((int)sB) & 1) != 0;
    int  kBe  = oddB ? kB : 8;

    // yB = fB + (addB + 0.5): exact half-int adds (proven)
    float stepB_h = stepB + 0.5f;
    float d0 = 0.f, d1 = 0.f;
    float yB[8];
#pragma unroll
    for (int i = 0; i < 8; i++) {
        float addBh = (i == kBe) ? stepB_h : 0.5f;
        yB[i] = fB[i] + addBh;
        float a  = (i == kAe) ? rcA : rA[i];
        float rb = x[i] - yB[i];
        d0 = __fadd_rn(d0, __fmul_rn(a, a));   // reference sequential order
        d1 = __fadd_rn(d1, __fmul_rn(rb, rb));
    }
    bool p0 = d0 < d1;
#pragma unroll
    for (int i = 0; i < 8; i++) {
        float oA = fA[i];
        if (i == kAe) oA += stepA;
        out[i] = p0 ? oA : yB[i];
    }
}

// ---- exact-domain cp_e8 residuals: v = x - closest_point(x).
// Valid when x is on the 1/8 grid (+- absorbed eps on zero lanes):
// decode gq, and encode layers 1-2. ----
static __device__ __forceinline__ void cp_e8_x(const float x[8], float v[8]) {
    float fA[8], rA[8];
#pragma unroll
    for (int i = 0; i < 8; i++) {
        fA[i] = cround(x[i]);
        rA[i] = x[i] - fA[i];
    }
    float sA = tsum8(fA);
    float rkA; int kA;
    argmax8(rA, rkA, kA);
    float stepA = stepsign(rkA, x[0]);
    bool oddA = (((int)sA) & 1) != 0;
    int  kAe  = oddA ? kA : 8;
    float rcA = rkA - stepA;

    float fB[8], rB[8];
#pragma unroll
    for (int i = 0; i < 8; i++) {
        float xs = x[i] - 0.5f;    // exact on this domain (eps absorbed)
        fB[i] = cround(xs);
        rB[i] = xs - fB[i];
    }
    float sB = tsum8(fB);
    float rkB; int kB;
    argmax8(rB, rkB, kB);
    float stepB = stepsign(rkB, x[0] - 0.5f);
    bool oddB = (((int)sB) & 1) != 0;
    int  kBe  = oddB ? kB : 8;
    float rcB = rkB - stepB;

    // exact-domain distances: FMA + difference-of-squares tie adjustment
    float d0 = 0.f, d1 = 0.f;
#pragma unroll
    for (int i = 0; i < 8; i++) {
        d0 = __fmaf_rn(rA[i], rA[i], d0);
        d1 = __fmaf_rn(rB[i], rB[i], d1);
    }
    float adjA = __fmul_rn(stepA, rcA + rkA);   // == rk^2 - rc^2, exact
    float adjB = __fmul_rn(stepB, rcB + rkB);
    d0 = oddA ? (d0 - adjA) : d0;
    d1 = oddB ? (d1 - adjB) : d1;
    bool p0 = d0 < d1;

    int   ksel = p0 ? kAe : kBe;
    float rcs  = p0 ? rcA : rcB;
#pragma unroll
    for (int i = 0; i < 8; i++) {
        float rs = p0 ? rA[i] : rB[i];
        v[i] = (i == ksel) ? rcs : rs;
    }
}

__global__ void __launch_bounds__(256)
lq_kernel(const float4* __restrict__ xin,
          const float* __restrict__ betap,
          const float4* __restrict__ eps4p,
          float4* __restrict__ outp,
          int nrows)
{
    int row = blockIdx.x * blockDim.x + threadIdx.x;
    if (row >= nrows) return;

    float beta = __ldg(betap);
    float4 e0 = __ldg(eps4p);
    float4 e1 = __ldg(eps4p + 1);
    float eps[8] = {e0.x, e0.y, e0.z, e0.w, e1.x, e1.y, e1.z, e1.w};

    float4 a0 = __ldg(xin + 2 * row);
    float4 a1 = __ldg(xin + 2 * row + 1);
    float x[8] = {a0.x, a0.y, a0.z, a0.w, a1.x, a1.y, a1.z, a1.w};

    bool beta1 = (beta == 1.0f);

    // layer-0 encode input: t = x/beta + eps (x/1.0 == x bitwise)
    float t[8];
#pragma unroll
    for (int i = 0; i < 8; i++) {
        float xl = beta1 ? x[i] : __fdiv_rn(x[i], beta);
        t[i] = xl + eps[i];
    }

    float xh[8];

#pragma unroll
    for (int m = 0; m < 3; m++) {
        // ---- encode layer m ----
        float cp[8];
        if (m == 0) {
            cp_e8_enc(t, cp);                  // continuous domain: ref order
        } else {
            float vv[8];
            cp_e8_x(t, vv);                    // t on 1/8 grid: exact domain
#pragma unroll
            for (int i = 0; i < 8; i++)
                cp[i] = t[i] - vv[i];          // exact lattice point
        }

        // z = cp @ G_inv (analytic forward solve; exact quarter-integers)
        float z[8];
        z[0] = 0.5f * cp[0];
        float sum06 = z[0];
#pragma unroll
        for (int i = 1; i < 7; i++) { z[i] = cp[i] + z[i - 1]; sum06 += z[i]; }
        z[7] = 2.f * cp[7] - sum06;

        // b = custom_round(fmod(z,4)); fmod exact; cround REQUIRED
        float b[8];
#pragma unroll
        for (int i = 0; i < 8; i++) {
            float q = truncf(z[i] * 0.25f);
            float r = __fmaf_rn(-4.f, q, z[i]);   // exact (dyadic)
            b[i] = cround(r);
        }

        // next layer input: t = fma(cp, 1/Q, eps) == fl(fl(cp*0.25)+eps)
        if (m < 2) {
#pragma unroll
            for (int i = 0; i < 8; i++)
                t[i] = __fmaf_rn(cp[i], 0.25f, eps[i]);
        }

        // ---- decode layer m: xi = g - 4*cp_e8(g/4) == 4*v ----
        float h = 0.5f * b[7];
        float g[8];
        g[0] = 2.f * b[0] - b[1] + h;
#pragma unroll
        for (int j = 1; j < 6; j++) g[j] = b[j] - b[j + 1] + h;
        g[6] = b[6] + h;
        g[7] = h;

        float gq[8];
#pragma unroll
        for (int i = 0; i < 8; i++) gq[i] = g[i] * 0.25f;   // exact eighths
        float v[8];
        cp_e8_x(gq, v);

        // xh += 4^(m+1) * v — all exact dyadic
        if (m == 0) {
#pragma unroll
            for (int i = 0; i < 8; i++) xh[i] = __fmul_rn(4.f, v[i]);
        } else {
            float c4 = (m == 1) ? 16.f : 64.f;
#pragma unroll
            for (int i = 0; i < 8; i++)
                xh[i] = __fmaf_rn(c4, v[i], xh[i]);
        }
    }

    float4 o0, o1;
    if (beta1) {
        o0 = make_float4(xh[0], xh[1], xh[2], xh[3]);
        o1 = make_float4(xh[4], xh[5], xh[6], xh[7]);
    } else {
        o0 = make_float4(beta*xh[0], beta*xh[1], beta*xh[2], beta*xh[3]);
        o1 = make_float4(beta*xh[4], beta*xh[5], beta*xh[6], beta*xh[7]);
    }
    outp[2 * row]     = o0;
    outp[2 * row + 1] = o1;
}

extern "C" void kernel_launch(void* const* d_in, const int* in_sizes, int n_in,
                              void* d_out, int out_size)
{
    const float* x = (const float*)d_in[0];
    const float* beta = nullptr;
    const float* eps  = nullptr;
    for (int i = 1; i < n_in; i++) {
        if (in_sizes[i] == 1) beta = (const float*)d_in[i];
        else if (in_sizes[i] == 8) eps = (const float*)d_in[i];
    }
    int nrows = in_sizes[0] / 8;
    int threads = 256;
    int blocks = (nrows + threads - 1) / threads;
    lq_kernel<<<blocks, threads>>>((const float4*)x, beta, (const float4*)eps,
                                   (float4*)d_out, nrows);
}

// round 17
// speedup vs baseline: 1.0602x; 1.0097x over previous
#include <cuda_runtime.h>

// LatticeQuantizer: hierarchical nested E8 lattice quantize (M=3, Q=4).
// R17 = R16 + tree-split exact-domain distance chains (pure reorder of
// provably order-free sums; halves a 32-cyc serial FMA chain) + xs0 reuse.
// All decision numerics identical to R16 (passed, rel_err 0.0).

#define TINY_F 1.1920928955078125e-07f  // np.finfo(float32).eps

static __device__ __forceinline__ float cround(float x) {
    float s = copysignf(TINY_F, x);
    return floorf((x - s) + 0.5f);
}

// left-priority (FIRST max) tree argmax over 8 lanes (R13-proven)
static __device__ __forceinline__ void argmax8(const float r[8], float& rk, int& k)
{
    bool p01 = fabsf(r[1]) > fabsf(r[0]);
    float v01 = p01 ? r[1] : r[0];  int k01 = p01 ? 1 : 0;
    bool p23 = fabsf(r[3]) > fabsf(r[2]);
    float v23 = p23 ? r[3] : r[2];  int k23 = p23 ? 3 : 2;
    bool p45 = fabsf(r[5]) > fabsf(r[4]);
    float v45 = p45 ? r[5] : r[4];  int k45 = p45 ? 5 : 4;
    bool p67 = fabsf(r[7]) > fabsf(r[6]);
    float v67 = p67 ? r[7] : r[6];  int k67 = p67 ? 7 : 6;

    bool g0 = fabsf(v23) > fabsf(v01);
    float va = g0 ? v23 : v01;  int ka = g0 ? k23 : k01;
    bool g1 = fabsf(v67) > fabsf(v45);
    float vb = g1 ? v67 : v45;  int kb = g1 ? k67 : k45;

    bool gf = fabsf(vb) > fabsf(va);
    rk = gf ? vb : va;
    k  = gf ? kb : ka;
}

// step: rk>0 -> +1 ; rk<0 -> -1 ; rk==0 -> (x0>=0 ? -1 : +1)
static __device__ __forceinline__ float stepsign(float rk, float x0) {
    int sel = (rk == 0.f) ? (__float_as_int(x0) ^ 0x80000000)
                          : __float_as_int(rk);
    return __int_as_float((sel & 0x80000000) | 0x3f800000);
}

// exact 8-way tree sum (integers: any association bit-identical)
static __device__ __forceinline__ float tsum8(const float f[8]) {
    float s01 = f[0] + f[1], s23 = f[2] + f[3];
    float s45 = f[4] + f[5], s67 = f[6] + f[7];
    return (s01 + s23) + (s45 + s67);
}

// ---- layer-0 encode closest point (reference-order; R16-verbatim) ----
static __device__ __forceinline__ void cp_e8_enc(const float x[8], float out[8]) {
    float fA[8], rA[8];
#pragma unroll
    for (int i = 0; i < 8; i++) {
        fA[i] = cround(x[i]);
        rA[i] = x[i] - fA[i];      // exact
    }
    float sA = tsum8(fA);
    float rkA; int kA;
    argmax8(rA, rkA, kA);
    float stepA = stepsign(rkA, x[0]);
    bool oddA = (((int)sA) & 1) != 0;
    int  kAe  = oddA ? kA : 8;
    float rcA = rkA - stepA;

    float fB[8], rB[8], xs0;
#pragma unroll
    for (int i = 0; i < 8; i++) {
        float xs = x[i] - 0.5f;
        if (i == 0) xs0 = xs;
        fB[i] = cround(xs);
        rB[i] = xs - fB[i];
    }
    float sB = tsum8(fB);
    float rkB; int kB;
    argmax8(rB, rkB, kB);
    float stepB = stepsign(rkB, xs0);
    bool oddB = (((int)sB) & 1) != 0;
    int  kBe  = oddB ? kB : 8;

    // yB = fB + (addB + 0.5): exact half-int adds (proven)
    float stepB_h = stepB + 0.5f;
    float d0 = 0.f, d1 = 0.f;
    float yB[8];
#pragma unroll
    for (int i = 0; i < 8; i++) {
        float addBh = (i == kBe) ? stepB_h : 0.5f;
        yB[i] = fB[i] + addBh;
        float a  = (i == kAe) ? rcA : rA[i];
        float rb = x[i] - yB[i];
        d0 = __fadd_rn(d0, __fmul_rn(a, a));   // reference sequential order
        d1 = __fadd_rn(d1, __fmul_rn(rb, rb));
    }
    bool p0 = d0 < d1;
#pragma unroll
    for (int i = 0; i < 8; i++) {
        float oA = fA[i];
        if (i == kAe) oA += stepA;
        out[i] = p0 ? oA : yB[i];
    }
}

// ---- exact-domain cp_e8 residuals: v = x - closest_point(x).
// Valid on the 1/8 grid (+- absorbed eps lanes): encode layers 1-2, decode.
static __device__ __forceinline__ void cp_e8_x(const float x[8], float v[8]) {
    float fA[8], rA[8];
#pragma unroll
    for (int i = 0; i < 8; i++) {
        fA[i] = cround(x[i]);
        rA[i] = x[i] - fA[i];
    }
    float sA = tsum8(fA);
    float rkA; int kA;
    argmax8(rA, rkA, kA);
    float stepA = stepsign(rkA, x[0]);
    bool oddA = (((int)sA) & 1) != 0;
    int  kAe  = oddA ? kA : 8;
    float rcA = rkA - stepA;

    float fB[8], rB[8], xs0;
#pragma unroll
    for (int i = 0; i < 8; i++) {
        float xs = x[i] - 0.5f;    // exact on this domain
        if (i == 0) xs0 = xs;
        fB[i] = cround(xs);
        rB[i] = xs - fB[i];
    }
    float sB = tsum8(fB);
    float rkB; int kB;
    argmax8(rB, rkB, kB);
    float stepB = stepsign(rkB, xs0);
    bool oddB = (((int)sB) & 1) != 0;
    int  kBe  = oddB ? kB : 8;
    float rcB = rkB - stepB;

    // exact-domain distances: TREE-SPLIT FMA chains (order-free sums:
    // grid terms multiples of 1/64 with exact partials; eps^2 terms
    // ~1e-25 absorbed by any grid partial in any association) +
    // difference-of-squares tie adjustment (R15-proven).
    float d0a = 0.f, d0b = 0.f, d1a = 0.f, d1b = 0.f;
#pragma unroll
    for (int i = 0; i < 4; i++) {
        d0a = __fmaf_rn(rA[i],     rA[i],     d0a);
        d0b = __fmaf_rn(rA[i + 4], rA[i + 4], d0b);
        d1a = __fmaf_rn(rB[i],     rB[i],     d1a);
        d1b = __fmaf_rn(rB[i + 4], rB[i + 4], d1b);
    }
    float d0 = d0a + d0b;
    float d1 = d1a + d1b;
    float adjA = __fmul_rn(stepA, rcA + rkA);   // == rk^2 - rc^2, exact
    float adjB = __fmul_rn(stepB, rcB + rkB);
    d0 = oddA ? (d0 - adjA) : d0;
    d1 = oddB ? (d1 - adjB) : d1;
    bool p0 = d0 < d1;

    int   ksel = p0 ? kAe : kBe;
    float rcs  = p0 ? rcA : rcB;
#pragma unroll
    for (int i = 0; i < 8; i++) {
        float rs = p0 ? rA[i] : rB[i];
        v[i] = (i == ksel) ? rcs : rs;
    }
}

__global__ void __launch_bounds__(256)
lq_kernel(const float4* __restrict__ xin,
          const float* __restrict__ betap,
          const float4* __restrict__ eps4p,
          float4* __restrict__ outp,
          int nrows)
{
    int row = blockIdx.x * blockDim.x + threadIdx.x;
    if (row >= nrows) return;

    float beta = __ldg(betap);
    float4 e0 = __ldg(eps4p);
    float4 e1 = __ldg(eps4p + 1);
    float eps[8] = {e0.x, e0.y, e0.z, e0.w, e1.x, e1.y, e1.z, e1.w};

    float4 a0 = __ldg(xin + 2 * row);
    float4 a1 = __ldg(xin + 2 * row + 1);
    float x[8] = {a0.x, a0.y, a0.z, a0.w, a1.x, a1.y, a1.z, a1.w};

    bool beta1 = (beta == 1.0f);

    float t[8];
#pragma unroll
    for (int i = 0; i < 8; i++) {
        float xl = beta1 ? x[i] : __fdiv_rn(x[i], beta);
        t[i] = xl + eps[i];
    }

    float xh[8];

#pragma unroll
    for (int m = 0; m < 3; m++) {
        // ---- encode layer m ----
        float cp[8];
        if (m == 0) {
            cp_e8_enc(t, cp);                  // continuous domain: ref order
        } else {
            float vv[8];
            cp_e8_x(t, vv);                    // t on 1/8 grid: exact domain
#pragma unroll
            for (int i = 0; i < 8; i++)
                cp[i] = t[i] - vv[i];          // exact lattice point
        }

        // z = cp @ G_inv (analytic forward solve; exact quarter-integers)
        float z[8];
        z[0] = 0.5f * cp[0];
        float sum06 = z[0];
#pragma unroll
        for (int i = 1; i < 7; i++) { z[i] = cp[i] + z[i - 1]; sum06 += z[i]; }
        z[7] = 2.f * cp[7] - sum06;

        // b = custom_round(fmod(z,4)); fmod exact; cround REQUIRED
        float b[8];
#pragma unroll
        for (int i = 0; i < 8; i++) {
            float q = truncf(z[i] * 0.25f);
            float r = __fmaf_rn(-4.f, q, z[i]);   // exact (dyadic)
            b[i] = cround(r);
        }

        // next layer input: t = fma(cp, 1/Q, eps) == fl(fl(cp*0.25)+eps)
        if (m < 2) {
#pragma unroll
            for (int i = 0; i < 8; i++)
                t[i] = __fmaf_rn(cp[i], 0.25f, eps[i]);
        }

        // ---- decode layer m: xi = g - 4*cp_e8(g/4) == 4*v ----
        float h = 0.5f * b[7];
        float g[8];
        g[0] = 2.f * b[0] - b[1] + h;
#pragma unroll
        for (int j = 1; j < 6; j++) g[j] = b[j] - b[j + 1] + h;
        g[6] = b[6] + h;
        g[7] = h;

        float gq[8];
#pragma unroll
        for (int i = 0; i < 8; i++) gq[i] = g[i] * 0.25f;   // exact eighths
        float v[8];
        cp_e8_x(gq, v);

        if (m == 0) {
#pragma unroll
            for (int i = 0; i < 8; i++) xh[i] = __fmul_rn(4.f, v[i]);
        } else {
            float c4 = (m == 1) ? 16.f : 64.f;
#pragma unroll
            for (int i = 0; i < 8; i++)
                xh[i] = __fmaf_rn(c4, v[i], xh[i]);
        }
    }

    float4 o0, o1;
    if (beta1) {
        o0 = make_float4(xh[0], xh[1], xh[2], xh[3]);
        o1 = make_float4(xh[4], xh[5], xh[6], xh[7]);
    } else {
        o0 = make_float4(beta*xh[0], beta*xh[1], beta*xh[2], beta*xh[3]);
        o1 = make_float4(beta*xh[4], beta*xh[5], beta*xh[6], beta*xh[7]);
    }
    outp[2 * row]     = o0;
    outp[2 * row + 1] = o1;
}

extern "C" void kernel_launch(void* const* d_in, const int* in_sizes, int n_in,
                              void* d_out, int out_size)
{
    const float* x = (const float*)d_in[0];
    const float* beta = nullptr;
    const float* eps  = nullptr;
    for (int i = 1; i < n_in; i++) {
        if (in_sizes[i] == 1) beta = (const float*)d_in[i];
        else if (in_sizes[i] == 8) eps = (const float*)d_in[i];
    }
    int nrows = in_sizes[0] / 8;
    int threads = 256;
    int blocks = (nrows + threads - 1) / threads;
    lq_kernel<<<blocks, threads>>>((const float4*)x, beta, (const float4*)eps,
                                   (float4*)d_out, nrows);
}